// round 16
// baseline (speedup 1.0000x reference)
#include <cuda_runtime.h>
#include <cuda_fp16.h>
#include <math.h>
#include <stdint.h>

#define Tn 512
#define Dn 2048
#define Hn 32
#define KVn 8
#define DHn 64
#define In 7168
#define En 8
#define QKVn 3072   // (H + 2*KV) * DH
#define PADH 40     // GEMM smem row stride in halfs
#define PADA 72     // attention smem row stride in halfs (64 data + 8 pad)

// ---------------- scratch (device globals; no allocation allowed) ----------------
__device__ __align__(16) float g_res1[Tn * Dn];
__device__ __align__(16) float g_x[Tn * Dn];
__device__ __align__(16) float g_qkv[Tn * QKVn];
__device__ __align__(16) float g_attn[Tn * Dn];
__device__ __align__(16) float g_x2[Tn * Dn];
__device__ __align__(16) __half g_h1h[En * Tn * In];
__device__ __align__(16) float g_eo[Tn * 4 * Dn];
__device__ int   g_tok[En * Tn];
__device__ float g_wgt[En * Tn];
__device__ int   g_slot[En * Tn];
__device__ int   g_cnt[En];

// ================= helpers (sm_80-level features only) =================
__device__ __forceinline__ uint32_t smem_u32(const void* p) {
    uint32_t a;
    asm("{ .reg .u64 t; cvta.to.shared.u64 t, %1; cvt.u32.u64 %0, t; }" : "=r"(a) : "l"(p));
    return a;
}
__device__ __forceinline__ uint32_t pack_h2(float x, float y) {
    __half2 h = __floats2half2_rn(x, y);
    return *reinterpret_cast<uint32_t*>(&h);
}
__device__ __forceinline__ uint4 cvt8(float4 a, float4 b) {
    uint4 u;
    u.x = pack_h2(a.x, a.y); u.y = pack_h2(a.z, a.w);
    u.z = pack_h2(b.x, b.y); u.w = pack_h2(b.z, b.w);
    return u;
}
__device__ __forceinline__ void mma_f16(float* c, const uint32_t* a, const uint32_t* b) {
    asm volatile(
        "mma.sync.aligned.m16n8k16.row.col.f32.f16.f16.f32 "
        "{%0,%1,%2,%3}, {%4,%5,%6,%7}, {%8,%9}, {%0,%1,%2,%3};"
        : "+f"(c[0]), "+f"(c[1]), "+f"(c[2]), "+f"(c[3])
        : "r"(a[0]), "r"(a[1]), "r"(a[2]), "r"(a[3]), "r"(b[0]), "r"(b[1]));
}
__device__ __forceinline__ void ldsm_x4(uint32_t& r0, uint32_t& r1, uint32_t& r2, uint32_t& r3,
                                        uint32_t addr) {
    asm volatile("ldmatrix.sync.aligned.m8n8.x4.shared.b16 {%0,%1,%2,%3}, [%4];"
                 : "=r"(r0), "=r"(r1), "=r"(r2), "=r"(r3) : "r"(addr));
}
__device__ __forceinline__ void ldsm_x4_t(uint32_t& r0, uint32_t& r1, uint32_t& r2, uint32_t& r3,
                                          uint32_t addr) {
    asm volatile("ldmatrix.sync.aligned.m8n8.x4.trans.shared.b16 {%0,%1,%2,%3}, [%4];"
                 : "=r"(r0), "=r"(r1), "=r"(r2), "=r"(r3) : "r"(addr));
}

// ================= fp16 tensor-core GEMM =================
// MODE 0: plain split-K partials (fp32 A).
// MODE 1: dual-B fused w1/w3 (gather; silu epilogue -> fp16 C).
// MODE 2: MoE gemm2 split-K2 (fp16 A = g_h1h), weighted scatter to g_eo 4-slot.
template <int MODE, int NT, int KSPLIT>
__global__ void __launch_bounds__(512, 1) k_gemm(const float* __restrict__ A,
                                                 const float* __restrict__ B,
                                                 const float* __restrict__ B2,
                                                 float* __restrict__ C,
                                                 float* __restrict__ C2,
                                                 int M, int N, int Kstride) {
    constexpr int BNT = NT / 32;
    constexpr int NPAIR = BNT / 2;
    constexpr int WN = NT / 4;
    constexpr int NB = (MODE == 1) ? 2 : 1;
    constexpr int NBB = (MODE == 1) ? 2 : (NT / 128);
    constexpr int A_HALFS = 128 * PADH;
    constexpr int B_HALFS = NT * PADH;
    constexpr int STAGE_HALFS = A_HALFS + NB * B_HALFS;
    constexpr int STAGE_BYTES = STAGE_HALFS * 2;

    const int kh = (MODE == 2) ? (int)(blockIdx.z & 1) : ((MODE == 0) ? (int)blockIdx.z : 0);
    const int e  = (MODE == 0) ? 0 : ((MODE == 2) ? (int)(blockIdx.z >> 1) : (int)blockIdx.z);
    const int cnt = (MODE == 0) ? M : g_cnt[e];
    const int bm = blockIdx.x * 128;
    if (bm >= cnt) return;
    const int bn = blockIdx.y * NT;

    const float* Bp  = (MODE == 0) ? B  : B  + (size_t)e * N * Kstride;
    const float* Bp2 = (MODE == 1) ? B2 + (size_t)e * N * Kstride : nullptr;

    const int Klen = Kstride / KSPLIT;
    const int koff = kh * Klen;

    const int tid = threadIdx.x;
    const int wid = tid >> 5, lane = tid & 31;
    const int g = lane >> 2, t4 = lane & 3;
    const int wm = (wid & 3) * 32, wn = (wid >> 2) * WN;

    const int rows_avail = cnt - bm - wm;
    const int mtact = (rows_avail >= 32) ? 2 : ((rows_avail <= 0) ? 0 : ((rows_avail + 15) >> 4));

    extern __shared__ char smc[];
    const uint32_t smU = smem_u32(smc);

    const int arow = tid >> 2;
    const int acol = (tid & 3) * 8;

    const float* aSrc = nullptr;
    const __half* aSrcH = nullptr;
    {
        if (MODE == 0) {
            int ridx = bm + arow; if (ridx >= M) ridx = M - 1;
            aSrc = A + (size_t)ridx * Kstride + acol + koff;
        } else if (MODE == 1) {
            int idx = bm + arow;
            int tok = (idx < cnt) ? g_tok[e * Tn + idx] : g_tok[e * Tn];
            aSrc = A + (size_t)tok * Kstride + acol + koff;
        } else {
            int idx = bm + arow;
            aSrcH = (const __half*)A + ((size_t)e * Tn + idx) * (size_t)Kstride + acol + koff;
        }
    }
    const uint32_t aSts = (uint32_t)(arow * PADH + acol) * 2u;

    const float* bSrc[NBB];
    uint32_t bSts[NBB];
#pragma unroll
    for (int j = 0; j < NBB; j++) {
        const int rowoff = (MODE == 2) ? j * 128 : 0;
        const float* base = (MODE == 1 && j == 1) ? Bp2 : Bp;
        const int moff = (MODE == 1 && j == 1) ? 1 : 0;
        bSrc[j] = base + (size_t)(bn + rowoff + arow) * Kstride + acol + koff;
        bSts[j] = (uint32_t)(A_HALFS + moff * B_HALFS + (rowoff + arow) * PADH + acol) * 2u;
    }

    const int l4 = lane >> 3, lr = lane & 7;
    uint32_t aAddr[2];
#pragma unroll
    for (int mt = 0; mt < 2; mt++) {
        int m_local = wm + mt * 16 + (l4 & 1) * 8 + lr;
        aAddr[mt] = smU + (uint32_t)(m_local * PADH) * 2u + (uint32_t)(l4 >> 1) * 16u;
    }
    uint32_t bAddr[NPAIR];
#pragma unroll
    for (int p = 0; p < NPAIR; p++) {
        int n_local = wn + p * 16 + (l4 >> 1) * 8 + lr;
        bAddr[p] = smU + (uint32_t)(A_HALFS + n_local * PADH) * 2u + (uint32_t)(l4 & 1) * 16u;
    }

    float acc[2][BNT][4];
    float acc2[MODE == 1 ? 2 : 1][MODE == 1 ? BNT : 1][4];
#pragma unroll
    for (int mt = 0; mt < 2; mt++)
#pragma unroll
        for (int nt = 0; nt < BNT; nt++)
#pragma unroll
            for (int q = 0; q < 4; q++) acc[mt][nt][q] = 0.f;
    if (MODE == 1) {
#pragma unroll
        for (int mt = 0; mt < 2; mt++)
#pragma unroll
            for (int nt = 0; nt < BNT; nt++)
#pragma unroll
                for (int q = 0; q < 4; q++) acc2[mt][nt][q] = 0.f;
    }

    float4 ra0, ra1;
    uint4 raH;
    float4 rb0[NBB], rb1[NBB];

#define LDG_STAGE(ktn)                                                   \
    do {                                                                 \
        const int k0 = (ktn) * 32;                                       \
        if (MODE == 2) {                                                 \
            raH = *(const uint4*)(aSrcH + k0);                           \
        } else {                                                         \
            ra0 = *(const float4*)(aSrc + k0);                           \
            ra1 = *(const float4*)(aSrc + k0 + 4);                       \
        }                                                                \
        _Pragma("unroll")                                                \
        for (int j = 0; j < NBB; j++) {                                  \
            rb0[j] = *(const float4*)(bSrc[j] + k0);                     \
            rb1[j] = *(const float4*)(bSrc[j] + k0 + 4);                 \
        }                                                                \
    } while (0)

#define STS_STAGE(ktn)                                                   \
    do {                                                                 \
        char* sb = smc + ((ktn) & 1) * STAGE_BYTES;                      \
        if (MODE == 2) *(uint4*)(sb + aSts) = raH;                       \
        else           *(uint4*)(sb + aSts) = cvt8(ra0, ra1);            \
        _Pragma("unroll")                                                \
        for (int j = 0; j < NBB; j++)                                    \
            *(uint4*)(sb + bSts[j]) = cvt8(rb0[j], rb1[j]);              \
    } while (0)

    const int KT = Klen / 32;

    LDG_STAGE(0);
    STS_STAGE(0);
    __syncthreads();
    LDG_STAGE(1);

    for (int kt = 0; kt < KT; kt++) {
        const uint32_t so = (uint32_t)(kt & 1) * STAGE_BYTES;
#pragma unroll
        for (int ks = 0; ks < 2; ks++) {
            const uint32_t kso = so + (uint32_t)ks * 32u;
            uint32_t af[2][4];
#pragma unroll
            for (int mt = 0; mt < 2; mt++)
                if (mt < mtact)
                    ldsm_x4(af[mt][0], af[mt][1], af[mt][2], af[mt][3], aAddr[mt] + kso);
            if (mtact > 0) {
                uint32_t bf[BNT][2];
#pragma unroll
                for (int p = 0; p < NPAIR; p++)
                    ldsm_x4(bf[2 * p][0], bf[2 * p][1], bf[2 * p + 1][0], bf[2 * p + 1][1],
                            bAddr[p] + kso);
#pragma unroll
                for (int mt = 0; mt < 2; mt++)
                    if (mt < mtact)
#pragma unroll
                        for (int nt = 0; nt < BNT; nt++)
                            mma_f16(acc[mt][nt], af[mt], bf[nt]);
                if (MODE == 1) {
                    uint32_t bg[BNT][2];
#pragma unroll
                    for (int p = 0; p < NPAIR; p++)
                        ldsm_x4(bg[2 * p][0], bg[2 * p][1], bg[2 * p + 1][0], bg[2 * p + 1][1],
                                bAddr[p] + (uint32_t)(B_HALFS * 2) + kso);
#pragma unroll
                    for (int mt = 0; mt < 2; mt++)
                        if (mt < mtact)
#pragma unroll
                            for (int nt = 0; nt < BNT; nt++)
                                mma_f16(acc2[mt][nt], af[mt], bg[nt]);
                }
            }
        }
        if (kt + 1 < KT) {
            STS_STAGE(kt + 1);
            if (kt + 2 < KT) LDG_STAGE(kt + 2);
            __syncthreads();
        }
    }
#undef LDG_STAGE
#undef STS_STAGE

#pragma unroll
    for (int mt = 0; mt < 2; mt++) {
        if (mt >= mtact) continue;
#pragma unroll
        for (int h = 0; h < 2; h++) {
            const int ridx = bm + wm + mt * 16 + g + h * 8;
            bool valid;
            float* dst = nullptr;
            __half* dsth = nullptr;
            float wg = 1.f;
            if (MODE == 0) {
                valid = ridx < M;
                if (valid) dst = C + (size_t)kh * M * N + (size_t)ridx * N;
            } else if (MODE == 1) {
                valid = ridx < cnt;
                if (valid) dsth = (__half*)C + ((size_t)e * Tn + ridx) * (size_t)N;
            } else {
                valid = ridx < cnt;
                if (valid) {
                    int idx = e * Tn + ridx;
                    int tok = g_tok[idx];
                    wg = g_wgt[idx];
                    int sl = g_slot[idx];
                    dst = C + ((size_t)tok * 4 + sl * 2 + kh) * (size_t)Dn;
                }
            }
            if (!valid) continue;
#pragma unroll
            for (int nt = 0; nt < BNT; nt++) {
                const int col = bn + wn + nt * 8 + 2 * t4;
                float2 v = make_float2(acc[mt][nt][h * 2 + 0], acc[mt][nt][h * 2 + 1]);
                if (MODE == 1) {
                    float b0 = acc2[mt][nt][h * 2 + 0];
                    float b1 = acc2[mt][nt][h * 2 + 1];
                    v.x = (v.x / (1.f + __expf(-v.x))) * b0;
                    v.y = (v.y / (1.f + __expf(-v.y))) * b1;
                    *(__half2*)(dsth + col) = __floats2half2_rn(v.x, v.y);
                } else {
                    if (MODE == 2) { v.x *= wg; v.y *= wg; }
                    *(float2*)(dst + col) = v;
                }
            }
        }
    }
}

// ================= flash attention (128 q-rows, 256 threads) =================
__global__ void __launch_bounds__(256, 1) k_flash() {
    const int qt = blockIdx.x;    // 0..3
    const int h = blockIdx.y;
    const int tid = threadIdx.x;
    const int wid = tid >> 5, lane = tid & 31;
    const int g = lane >> 2, t4 = lane & 3;
    const int kvh = h >> 2;

    __shared__ __align__(16) __half Qs[128 * PADA];
    __shared__ __align__(16) __half Ks[64 * PADA];
    __shared__ __align__(16) __half Vs[64 * PADA];
    const uint32_t qU = smem_u32(Qs);
    const uint32_t kU = smem_u32(Ks);
    const uint32_t vU = smem_u32(Vs);

    for (int idx = tid; idx < 128 * 8; idx += 256) {
        int row = idx >> 3, c8 = (idx & 7) * 8;
        const float* src = g_qkv + (size_t)(qt * 128 + row) * QKVn + h * 64 + c8;
        *(uint4*)((char*)Qs + (row * PADA + c8) * 2) =
            cvt8(*(const float4*)src, *(const float4*)(src + 4));
    }
    __syncthreads();

    const int l4 = lane >> 3, lr = lane & 7;
    uint32_t qf[4][4];
    {
        int m_local = wid * 16 + (l4 & 1) * 8 + lr;
        uint32_t qAddr = qU + (uint32_t)(m_local * PADA) * 2u + (uint32_t)(l4 >> 1) * 16u;
#pragma unroll
        for (int kc = 0; kc < 4; kc++)
            ldsm_x4(qf[kc][0], qf[kc][1], qf[kc][2], qf[kc][3], qAddr + (uint32_t)kc * 32u);
    }

    uint32_t kA[4];
#pragma unroll
    for (int p = 0; p < 4; p++) {
        int n_local = p * 16 + (l4 >> 1) * 8 + lr;
        kA[p] = kU + (uint32_t)(n_local * PADA) * 2u + (uint32_t)(l4 & 1) * 16u;
    }
    uint32_t vA[4];
#pragma unroll
    for (int p = 0; p < 4; p++) {
        int k_row = (l4 & 1) * 8 + lr;
        int dh_c = p * 16 + (l4 >> 1) * 8;
        vA[p] = vU + (uint32_t)(k_row * PADA + dh_c) * 2u;
    }

    float o[8][4];
#pragma unroll
    for (int dt = 0; dt < 8; dt++)
#pragma unroll
        for (int q = 0; q < 4; q++) o[dt][q] = 0.f;
    float mrow[2] = {-3.4e38f, -3.4e38f};
    float lrow[2] = {0.f, 0.f};

    const int row0 = qt * 128 + wid * 16 + g;
    const int ktmax = 2 * qt + 1;

    for (int kt = 0; kt <= ktmax; kt++) {
        for (int idx = tid; idx < 64 * 8; idx += 256) {
            int row = idx >> 3, c8 = (idx & 7) * 8;
            const float* srck = g_qkv + (size_t)(kt * 64 + row) * QKVn + 2048 + kvh * 64 + c8;
            *(uint4*)((char*)Ks + (row * PADA + c8) * 2) =
                cvt8(*(const float4*)srck, *(const float4*)(srck + 4));
            const float* srcv = g_qkv + (size_t)(kt * 64 + row) * QKVn + 2560 + kvh * 64 + c8;
            *(uint4*)((char*)Vs + (row * PADA + c8) * 2) =
                cvt8(*(const float4*)srcv, *(const float4*)(srcv + 4));
        }
        __syncthreads();

        float s[8][4];
#pragma unroll
        for (int nt = 0; nt < 8; nt++)
#pragma unroll
            for (int q = 0; q < 4; q++) s[nt][q] = 0.f;
#pragma unroll
        for (int kc = 0; kc < 4; kc++) {
            uint32_t bf[8][2];
#pragma unroll
            for (int p = 0; p < 4; p++)
                ldsm_x4(bf[2 * p][0], bf[2 * p][1], bf[2 * p + 1][0], bf[2 * p + 1][1],
                        kA[p] + (uint32_t)kc * 32u);
#pragma unroll
            for (int nt = 0; nt < 8; nt++)
                mma_f16(s[nt], qf[kc], bf[nt]);
        }

        float alpha[2];
#pragma unroll
        for (int r = 0; r < 2; r++) {
            const int rown = row0 + r * 8;
            float mx = mrow[r];
#pragma unroll
            for (int nt = 0; nt < 8; nt++)
#pragma unroll
                for (int q = 0; q < 2; q++) {
                    int col = kt * 64 + nt * 8 + 2 * t4 + q;
                    float val = (col <= rown) ? s[nt][r * 2 + q] * 0.125f : -1e30f;
                    s[nt][r * 2 + q] = val;
                    mx = fmaxf(mx, val);
                }
            mx = fmaxf(mx, __shfl_xor_sync(0xffffffffu, mx, 1));
            mx = fmaxf(mx, __shfl_xor_sync(0xffffffffu, mx, 2));
            alpha[r] = __expf(mrow[r] - mx);
            float ls = 0.f;
#pragma unroll
            for (int nt = 0; nt < 8; nt++)
#pragma unroll
                for (int q = 0; q < 2; q++) {
                    float p = __expf(s[nt][r * 2 + q] - mx);
                    s[nt][r * 2 + q] = p;
                    ls += p;
                }
            ls += __shfl_xor_sync(0xffffffffu, ls, 1);
            ls += __shfl_xor_sync(0xffffffffu, ls, 2);
            lrow[r] = lrow[r] * alpha[r] + ls;
            mrow[r] = mx;
        }
#pragma unroll
        for (int dt = 0; dt < 8; dt++) {
            o[dt][0] *= alpha[0]; o[dt][1] *= alpha[0];
            o[dt][2] *= alpha[1]; o[dt][3] *= alpha[1];
        }

        uint32_t pf[4][4];
#pragma unroll
        for (int j = 0; j < 4; j++) {
            pf[j][0] = pack_h2(s[2 * j][0], s[2 * j][1]);
            pf[j][1] = pack_h2(s[2 * j][2], s[2 * j][3]);
            pf[j][2] = pack_h2(s[2 * j + 1][0], s[2 * j + 1][1]);
            pf[j][3] = pack_h2(s[2 * j + 1][2], s[2 * j + 1][3]);
        }
#pragma unroll
        for (int j = 0; j < 4; j++) {
            uint32_t vf[8][2];
#pragma unroll
            for (int p = 0; p < 4; p++)
                ldsm_x4_t(vf[2 * p][0], vf[2 * p][1], vf[2 * p + 1][0], vf[2 * p + 1][1],
                          vA[p] + (uint32_t)(j * 16 * PADA) * 2u);
#pragma unroll
            for (int dt = 0; dt < 8; dt++)
                mma_f16(o[dt], pf[j], vf[dt]);
        }
        __syncthreads();
    }

    float inv0 = 1.f / lrow[0];
    float inv1 = 1.f / lrow[1];
#pragma unroll
    for (int r = 0; r < 2; r++) {
        const int row = row0 + r * 8;
        float invr = r ? inv1 : inv0;
#pragma unroll
        for (int dt = 0; dt < 8; dt++) {
            int col = dt * 8 + 2 * t4;
            float* p = &g_attn[(size_t)row * Dn + h * 64 + col];
            p[0] = o[dt][r * 2 + 0] * invr;
            p[1] = o[dt][r * 2 + 1] * invr;
        }
    }
}

// ---------------- small utility kernels ----------------

__global__ void k_add_rmsnorm(const float* __restrict__ h, const float* __restrict__ r,
                              const float* __restrict__ w) {
    int t = blockIdx.x;
    if (t == 0 && threadIdx.x < En) g_cnt[threadIdx.x] = 0;
    const float* hr = h + t * Dn;
    const float* rr = r + t * Dn;
    float* resr = g_res1 + t * Dn;
    float* xr = g_x + t * Dn;

    float v[8];
    float local = 0.f;
#pragma unroll
    for (int j = 0; j < 8; j++) {
        int c = threadIdx.x + j * 256;
        float s = hr[c] + rr[c];
        v[j] = s;
        resr[c] = s;
        local += s * s;
    }
#pragma unroll
    for (int o = 16; o > 0; o >>= 1) local += __shfl_xor_sync(0xffffffffu, local, o);
    __shared__ float red[8];
    if ((threadIdx.x & 31) == 0) red[threadIdx.x >> 5] = local;
    __syncthreads();
    __shared__ float inv;
    if (threadIdx.x == 0) {
        float s = 0.f;
#pragma unroll
        for (int i = 0; i < 8; i++) s += red[i];
        inv = rsqrtf(s / (float)Dn + 1e-5f);
    }
    __syncthreads();
    float iv = inv;
#pragma unroll
    for (int j = 0; j < 8; j++) {
        int c = threadIdx.x + j * 256;
        xr[c] = v[j] * iv * w[c];
    }
}

__global__ void k_add2_rmsnorm_gate(const float* __restrict__ p0, const float* __restrict__ p1,
                                    const float* __restrict__ w, float* __restrict__ res2out,
                                    const float* __restrict__ gw) {
    int t = blockIdx.x;
    const float* a0 = p0 + t * Dn;
    const float* a1 = p1 + t * Dn;
    const float* rr = g_res1 + t * Dn;
    float* ro = res2out + t * Dn;
    float* xr = g_x2 + t * Dn;
    __shared__ float xs[Dn];
    float v[8];
    float local = 0.f;
#pragma unroll
    for (int j = 0; j < 8; j++) {
        int c = threadIdx.x + j * 256;
        float s = a0[c] + a1[c] + rr[c];
        v[j] = s;
        ro[c] = s;
        local += s * s;
    }
#pragma unroll
    for (int o = 16; o > 0; o >>= 1) local += __shfl_xor_sync(0xffffffffu, local, o);
    __shared__ float red[8];
    if ((threadIdx.x & 31) == 0) red[threadIdx.x >> 5] = local;
    __syncthreads();
    __shared__ float inv;
    if (threadIdx.x == 0) {
        float s = 0.f;
#pragma unroll
        for (int i = 0; i < 8; i++) s += red[i];
        inv = rsqrtf(s / (float)Dn + 1e-5f);
    }
    __syncthreads();
    float iv = inv;
#pragma unroll
    for (int j = 0; j < 8; j++) {
        int c = threadIdx.x + j * 256;
        float xv = v[j] * iv * w[c];
        xr[c] = xv;
        xs[c] = xv;
    }
    __syncthreads();

    const int warp = threadIdx.x >> 5, lane = threadIdx.x & 31;
    const float* wr = gw + (size_t)warp * Dn;
    float s = 0.f;
    for (int c = lane; c < Dn; c += 32) s += xs[c] * wr[c];
#pragma unroll
    for (int o = 16; o > 0; o >>= 1) s += __shfl_xor_sync(0xffffffffu, s, o);
    __shared__ float lg[En];
    if (lane == 0) lg[warp] = s;
    __syncthreads();
    if (threadIdx.x == 0) {
        int i0 = 0;
        for (int e = 1; e < En; e++) if (lg[e] > lg[i0]) i0 = e;
        int i1 = (i0 == 0) ? 1 : 0;
        for (int e = 0; e < En; e++) if (e != i0 && lg[e] > lg[i1]) i1 = e;
        float w1v = __expf(lg[i1] - lg[i0]);
        float invw = 1.f / (1.f + w1v);
        float w0 = invw, w1n = w1v * invw;
        int pp0 = atomicAdd(&g_cnt[i0], 1);
        g_tok[i0 * Tn + pp0] = t; g_wgt[i0 * Tn + pp0] = w0; g_slot[i0 * Tn + pp0] = 0;
        int pp1 = atomicAdd(&g_cnt[i1], 1);
        g_tok[i1 * Tn + pp1] = t; g_wgt[i1 * Tn + pp1] = w1n; g_slot[i1 * Tn + pp1] = 1;
    }
}

// sum qkv split-K partials (from g_eo) + apply rope, write g_qkv.
// idx covers t (512) x head hh (48) x pair d (32); v heads (hh>=40) just sum.
__global__ void k_rope_sum(const float* __restrict__ p,
                           const float* __restrict__ cosb, const float* __restrict__ sinb) {
    int idx = blockIdx.x * 256 + threadIdx.x;
    if (idx >= Tn * 48 * 32) return;
    int d = idx & 31;
    int rest = idx >> 5;
    int hh = rest % 48;
    int t = rest / 48;
    size_t off = (size_t)t * QKVn + hh * 64 + d;
    float x1 = p[off] + p[off + (size_t)Tn * QKVn];
    float x2 = p[off + 32] + p[off + 32 + (size_t)Tn * QKVn];
    float* dst = g_qkv + off;
    if (hh < 40) {
        float c = cosb[t * 32 + d];
        float s = sinb[t * 32 + d];
        dst[0]  = x1 * c - x2 * s;
        dst[32] = x2 * c + x1 * s;
    } else {
        dst[0]  = x1;
        dst[32] = x2;
    }
}

// moe_out = sum of 4 eo slots (2 experts x 2 K-halves), float4 vectorized
__global__ void k_combine(float* __restrict__ out) {
    int i4 = blockIdx.x * 256 + threadIdx.x;      // float4 index
    if (i4 >= (Tn * Dn) / 4) return;
    int t = i4 / (Dn / 4);
    int d = i4 - t * (Dn / 4);
    const float4* base = (const float4*)(g_eo + (size_t)t * 4 * Dn) + d;
    float4 a = base[0];
    float4 b = base[Dn / 4];
    float4 c = base[2 * Dn / 4];
    float4 e = base[3 * Dn / 4];
    ((float4*)out)[i4] = make_float4(a.x + b.x + c.x + e.x, a.y + b.y + c.y + e.y,
                                     a.z + b.z + c.z + e.z, a.w + b.w + c.w + e.w);
}

// ---------------- launch ----------------
extern "C" void kernel_launch(void* const* d_in, const int* in_sizes, int n_in,
                              void* d_out, int out_size) {
    const float* hs   = (const float*)d_in[0];
    const float* resi = (const float*)d_in[1];
    const float* cosb = (const float*)d_in[2];
    const float* sinb = (const float*)d_in[3];
    const float* ln1  = (const float*)d_in[4];
    const float* ln2  = (const float*)d_in[5];
    const float* wqkv = (const float*)d_in[6];
    const float* wo   = (const float*)d_in[7];
    const float* gw   = (const float*)d_in[8];
    const float* w1   = (const float*)d_in[9];
    const float* w3   = (const float*)d_in[10];
    const float* w2   = (const float*)d_in[11];

    float* out = (float*)d_out;
    float* moe_out = out;
    float* res2 = out + Tn * Dn;

    void *px, *pattn, *px2, *ph1h, *peo;
    cudaGetSymbolAddress(&px, g_x);
    cudaGetSymbolAddress(&pattn, g_attn);
    cudaGetSymbolAddress(&px2, g_x2);
    cudaGetSymbolAddress(&ph1h, g_h1h);
    cudaGetSymbolAddress(&peo, g_eo);

    constexpr int SMEM0 = 2 * (128 * PADH + 128 * PADH) * 2;       // 40960
    constexpr int SMEM1 = 2 * (128 * PADH + 2 * 128 * PADH) * 2;   // 61440
    constexpr int SMEM2 = 2 * (128 * PADH + 256 * PADH) * 2;       // 61440
    cudaFuncSetAttribute(k_gemm<0, 128, 2>, cudaFuncAttributeMaxDynamicSharedMemorySize, SMEM0);
    cudaFuncSetAttribute(k_gemm<1, 128, 1>, cudaFuncAttributeMaxDynamicSharedMemorySize, SMEM1);
    cudaFuncSetAttribute(k_gemm<2, 256, 2>, cudaFuncAttributeMaxDynamicSharedMemorySize, SMEM2);

    k_add_rmsnorm<<<Tn, 256>>>(hs, resi, ln1);

    // qkv split-K2 partials -> g_eo; fused sum + rope -> g_qkv
    k_gemm<0, 128, 2><<<dim3(Tn / 128, QKVn / 128, 2), 512, SMEM0>>>(
        (const float*)px, wqkv, nullptr, (float*)peo, nullptr, Tn, QKVn, Dn);
    k_rope_sum<<<(Tn * 48 * 32) / 256, 256>>>((const float*)peo, cosb, sinb);

    // fused flash attention (scores + softmax + P@V), 128-row q tiles
    k_flash<<<dim3(Tn / 128, Hn), 256>>>();

    // attn @ wo^T partials: [2][512][2048] into g_eo; fused add + rmsnorm + gate
    k_gemm<0, 128, 2><<<dim3(Tn / 128, Dn / 128, 2), 512, SMEM0>>>(
        (const float*)pattn, wo, nullptr, (float*)peo, nullptr, Tn, Dn, Dn);
    k_add2_rmsnorm_gate<<<Tn, 256>>>((const float*)peo, (const float*)peo + Tn * Dn,
                                     ln2, res2, gw);

    // fused dual-B grouped GEMM1: h1h = fp16( silu(x@w1^T) * (x@w3^T) )
    k_gemm<1, 128, 1><<<dim3(Tn / 128, In / 128, En), 512, SMEM1>>>(
        (const float*)px2, w1, w3, (float*)ph1h, nullptr, Tn, In, Dn);
    // w2 grouped GEMM (fp16 A), split-K2, scatter into 4-slot eo
    k_gemm<2, 256, 2><<<dim3(Tn / 128, Dn / 256, En * 2), 512, SMEM2>>>(
        (const float*)ph1h, w2, nullptr, (float*)peo, nullptr, Tn, Dn, In);
    k_combine<<<(Tn * Dn / 4 + 255) / 256, 256>>>(moe_out);
}

// round 17
// speedup vs baseline: 1.0030x; 1.0030x over previous
#include <cuda_runtime.h>
#include <cuda_fp16.h>
#include <math.h>
#include <stdint.h>

#define Tn 512
#define Dn 2048
#define Hn 32
#define KVn 8
#define DHn 64
#define In 7168
#define En 8
#define QKVn 3072   // (H + 2*KV) * DH
#define PADH 40     // GEMM smem row stride in halfs
#define PADA 72     // attention smem row stride in halfs (64 data + 8 pad)

// ---------------- scratch (device globals; no allocation allowed) ----------------
__device__ __align__(16) float g_res1[Tn * Dn];
__device__ __align__(16) float g_x[Tn * Dn];
__device__ __align__(16) float g_qkv[Tn * QKVn];
__device__ __align__(16) float g_attn[Tn * Dn];
__device__ __align__(16) float g_x2[Tn * Dn];
__device__ __align__(16) __half g_h1h[En * Tn * In];
__device__ __align__(16) float g_eo[Tn * 4 * Dn];
__device__ int   g_tok[En * Tn];
__device__ float g_wgt[En * Tn];
__device__ int   g_slot[En * Tn];
__device__ int   g_cnt[En];

// ================= helpers (sm_80-level features only) =================
__device__ __forceinline__ uint32_t smem_u32(const void* p) {
    uint32_t a;
    asm("{ .reg .u64 t; cvta.to.shared.u64 t, %1; cvt.u32.u64 %0, t; }" : "=r"(a) : "l"(p));
    return a;
}
__device__ __forceinline__ uint32_t pack_h2(float x, float y) {
    __half2 h = __floats2half2_rn(x, y);
    return *reinterpret_cast<uint32_t*>(&h);
}
__device__ __forceinline__ uint4 cvt8(float4 a, float4 b) {
    uint4 u;
    u.x = pack_h2(a.x, a.y); u.y = pack_h2(a.z, a.w);
    u.z = pack_h2(b.x, b.y); u.w = pack_h2(b.z, b.w);
    return u;
}
__device__ __forceinline__ void mma_f16(float* c, const uint32_t* a, const uint32_t* b) {
    asm volatile(
        "mma.sync.aligned.m16n8k16.row.col.f32.f16.f16.f32 "
        "{%0,%1,%2,%3}, {%4,%5,%6,%7}, {%8,%9}, {%0,%1,%2,%3};"
        : "+f"(c[0]), "+f"(c[1]), "+f"(c[2]), "+f"(c[3])
        : "r"(a[0]), "r"(a[1]), "r"(a[2]), "r"(a[3]), "r"(b[0]), "r"(b[1]));
}
__device__ __forceinline__ void ldsm_x4(uint32_t& r0, uint32_t& r1, uint32_t& r2, uint32_t& r3,
                                        uint32_t addr) {
    asm volatile("ldmatrix.sync.aligned.m8n8.x4.shared.b16 {%0,%1,%2,%3}, [%4];"
                 : "=r"(r0), "=r"(r1), "=r"(r2), "=r"(r3) : "r"(addr));
}
__device__ __forceinline__ void ldsm_x4_t(uint32_t& r0, uint32_t& r1, uint32_t& r2, uint32_t& r3,
                                          uint32_t addr) {
    asm volatile("ldmatrix.sync.aligned.m8n8.x4.trans.shared.b16 {%0,%1,%2,%3}, [%4];"
                 : "=r"(r0), "=r"(r1), "=r"(r2), "=r"(r3) : "r"(addr));
}

// ================= fp16 tensor-core GEMM =================
// MODE 0: plain split-K partials (fp32 A).
// MODE 1: dual-B fused w1/w3 (gather; silu epilogue -> fp16 C).
// MODE 2: MoE gemm2 split-K2 (fp16 A = g_h1h), weighted scatter to g_eo 4-slot.
template <int MODE, int NT, int KSPLIT>
__global__ void __launch_bounds__(512, 1) k_gemm(const float* __restrict__ A,
                                                 const float* __restrict__ B,
                                                 const float* __restrict__ B2,
                                                 float* __restrict__ C,
                                                 float* __restrict__ C2,
                                                 int M, int N, int Kstride) {
    constexpr int BNT = NT / 32;
    constexpr int NPAIR = BNT / 2;
    constexpr int WN = NT / 4;
    constexpr int NB = (MODE == 1) ? 2 : 1;
    constexpr int NBB = (MODE == 1) ? 2 : (NT / 128);
    constexpr int A_HALFS = 128 * PADH;
    constexpr int B_HALFS = NT * PADH;
    constexpr int STAGE_HALFS = A_HALFS + NB * B_HALFS;
    constexpr int STAGE_BYTES = STAGE_HALFS * 2;

    const int kh = (MODE == 2) ? (int)(blockIdx.z & 1) : ((MODE == 0) ? (int)blockIdx.z : 0);
    const int e  = (MODE == 0) ? 0 : ((MODE == 2) ? (int)(blockIdx.z >> 1) : (int)blockIdx.z);
    const int cnt = (MODE == 0) ? M : g_cnt[e];
    const int bm = blockIdx.x * 128;
    if (bm >= cnt) return;
    const int bn = blockIdx.y * NT;

    const float* Bp  = (MODE == 0) ? B  : B  + (size_t)e * N * Kstride;
    const float* Bp2 = (MODE == 1) ? B2 + (size_t)e * N * Kstride : nullptr;

    const int Klen = Kstride / KSPLIT;
    const int koff = kh * Klen;

    const int tid = threadIdx.x;
    const int wid = tid >> 5, lane = tid & 31;
    const int g = lane >> 2, t4 = lane & 3;
    const int wm = (wid & 3) * 32, wn = (wid >> 2) * WN;

    const int rows_avail = cnt - bm - wm;
    const int mtact = (rows_avail >= 32) ? 2 : ((rows_avail <= 0) ? 0 : ((rows_avail + 15) >> 4));

    extern __shared__ char smc[];
    const uint32_t smU = smem_u32(smc);

    const int arow = tid >> 2;
    const int acol = (tid & 3) * 8;

    const float* aSrc = nullptr;
    const __half* aSrcH = nullptr;
    {
        if (MODE == 0) {
            int ridx = bm + arow; if (ridx >= M) ridx = M - 1;
            aSrc = A + (size_t)ridx * Kstride + acol + koff;
        } else if (MODE == 1) {
            int idx = bm + arow;
            int tok = (idx < cnt) ? g_tok[e * Tn + idx] : g_tok[e * Tn];
            aSrc = A + (size_t)tok * Kstride + acol + koff;
        } else {
            int idx = bm + arow;
            aSrcH = (const __half*)A + ((size_t)e * Tn + idx) * (size_t)Kstride + acol + koff;
        }
    }
    const uint32_t aSts = (uint32_t)(arow * PADH + acol) * 2u;

    const float* bSrc[NBB];
    uint32_t bSts[NBB];
#pragma unroll
    for (int j = 0; j < NBB; j++) {
        const int rowoff = (MODE == 2) ? j * 128 : 0;
        const float* base = (MODE == 1 && j == 1) ? Bp2 : Bp;
        const int moff = (MODE == 1 && j == 1) ? 1 : 0;
        bSrc[j] = base + (size_t)(bn + rowoff + arow) * Kstride + acol + koff;
        bSts[j] = (uint32_t)(A_HALFS + moff * B_HALFS + (rowoff + arow) * PADH + acol) * 2u;
    }

    const int l4 = lane >> 3, lr = lane & 7;
    uint32_t aAddr[2];
#pragma unroll
    for (int mt = 0; mt < 2; mt++) {
        int m_local = wm + mt * 16 + (l4 & 1) * 8 + lr;
        aAddr[mt] = smU + (uint32_t)(m_local * PADH) * 2u + (uint32_t)(l4 >> 1) * 16u;
    }
    uint32_t bAddr[NPAIR];
#pragma unroll
    for (int p = 0; p < NPAIR; p++) {
        int n_local = wn + p * 16 + (l4 >> 1) * 8 + lr;
        bAddr[p] = smU + (uint32_t)(A_HALFS + n_local * PADH) * 2u + (uint32_t)(l4 & 1) * 16u;
    }

    float acc[2][BNT][4];
    float acc2[MODE == 1 ? 2 : 1][MODE == 1 ? BNT : 1][4];
#pragma unroll
    for (int mt = 0; mt < 2; mt++)
#pragma unroll
        for (int nt = 0; nt < BNT; nt++)
#pragma unroll
            for (int q = 0; q < 4; q++) acc[mt][nt][q] = 0.f;
    if (MODE == 1) {
#pragma unroll
        for (int mt = 0; mt < 2; mt++)
#pragma unroll
            for (int nt = 0; nt < BNT; nt++)
#pragma unroll
                for (int q = 0; q < 4; q++) acc2[mt][nt][q] = 0.f;
    }

    float4 ra0, ra1;
    uint4 raH;
    float4 rb0[NBB], rb1[NBB];

#define LDG_STAGE(ktn)                                                   \
    do {                                                                 \
        const int k0 = (ktn) * 32;                                       \
        if (MODE == 2) {                                                 \
            raH = *(const uint4*)(aSrcH + k0);                           \
        } else {                                                         \
            ra0 = *(const float4*)(aSrc + k0);                           \
            ra1 = *(const float4*)(aSrc + k0 + 4);                       \
        }                                                                \
        _Pragma("unroll")                                                \
        for (int j = 0; j < NBB; j++) {                                  \
            rb0[j] = *(const float4*)(bSrc[j] + k0);                     \
            rb1[j] = *(const float4*)(bSrc[j] + k0 + 4);                 \
        }                                                                \
    } while (0)

#define STS_STAGE(ktn)                                                   \
    do {                                                                 \
        char* sb = smc + ((ktn) & 1) * STAGE_BYTES;                      \
        if (MODE == 2) *(uint4*)(sb + aSts) = raH;                       \
        else           *(uint4*)(sb + aSts) = cvt8(ra0, ra1);            \
        _Pragma("unroll")                                                \
        for (int j = 0; j < NBB; j++)                                    \
            *(uint4*)(sb + bSts[j]) = cvt8(rb0[j], rb1[j]);              \
    } while (0)

    const int KT = Klen / 32;

    LDG_STAGE(0);
    STS_STAGE(0);
    __syncthreads();
    LDG_STAGE(1);

    for (int kt = 0; kt < KT; kt++) {
        const uint32_t so = (uint32_t)(kt & 1) * STAGE_BYTES;
#pragma unroll
        for (int ks = 0; ks < 2; ks++) {
            const uint32_t kso = so + (uint32_t)ks * 32u;
            uint32_t af[2][4];
#pragma unroll
            for (int mt = 0; mt < 2; mt++)
                if (mt < mtact)
                    ldsm_x4(af[mt][0], af[mt][1], af[mt][2], af[mt][3], aAddr[mt] + kso);
            if (mtact > 0) {
                uint32_t bf[BNT][2];
#pragma unroll
                for (int p = 0; p < NPAIR; p++)
                    ldsm_x4(bf[2 * p][0], bf[2 * p][1], bf[2 * p + 1][0], bf[2 * p + 1][1],
                            bAddr[p] + kso);
#pragma unroll
                for (int mt = 0; mt < 2; mt++)
                    if (mt < mtact)
#pragma unroll
                        for (int nt = 0; nt < BNT; nt++)
                            mma_f16(acc[mt][nt], af[mt], bf[nt]);
                if (MODE == 1) {
                    uint32_t bg[BNT][2];
#pragma unroll
                    for (int p = 0; p < NPAIR; p++)
                        ldsm_x4(bg[2 * p][0], bg[2 * p][1], bg[2 * p + 1][0], bg[2 * p + 1][1],
                                bAddr[p] + (uint32_t)(B_HALFS * 2) + kso);
#pragma unroll
                    for (int mt = 0; mt < 2; mt++)
                        if (mt < mtact)
#pragma unroll
                            for (int nt = 0; nt < BNT; nt++)
                                mma_f16(acc2[mt][nt], af[mt], bg[nt]);
                }
            }
        }
        if (kt + 1 < KT) {
            STS_STAGE(kt + 1);
            if (kt + 2 < KT) LDG_STAGE(kt + 2);
            __syncthreads();
        }
    }
#undef LDG_STAGE
#undef STS_STAGE

#pragma unroll
    for (int mt = 0; mt < 2; mt++) {
        if (mt >= mtact) continue;
#pragma unroll
        for (int h = 0; h < 2; h++) {
            const int ridx = bm + wm + mt * 16 + g + h * 8;
            bool valid;
            float* dst = nullptr;
            __half* dsth = nullptr;
            float wg = 1.f;
            if (MODE == 0) {
                valid = ridx < M;
                if (valid) dst = C + (size_t)kh * M * N + (size_t)ridx * N;
            } else if (MODE == 1) {
                valid = ridx < cnt;
                if (valid) dsth = (__half*)C + ((size_t)e * Tn + ridx) * (size_t)N;
            } else {
                valid = ridx < cnt;
                if (valid) {
                    int idx = e * Tn + ridx;
                    int tok = g_tok[idx];
                    wg = g_wgt[idx];
                    int sl = g_slot[idx];
                    dst = C + ((size_t)tok * 4 + sl * 2 + kh) * (size_t)Dn;
                }
            }
            if (!valid) continue;
#pragma unroll
            for (int nt = 0; nt < BNT; nt++) {
                const int col = bn + wn + nt * 8 + 2 * t4;
                float2 v = make_float2(acc[mt][nt][h * 2 + 0], acc[mt][nt][h * 2 + 1]);
                if (MODE == 1) {
                    float b0 = acc2[mt][nt][h * 2 + 0];
                    float b1 = acc2[mt][nt][h * 2 + 1];
                    v.x = (v.x / (1.f + __expf(-v.x))) * b0;
                    v.y = (v.y / (1.f + __expf(-v.y))) * b1;
                    *(__half2*)(dsth + col) = __floats2half2_rn(v.x, v.y);
                } else {
                    if (MODE == 2) { v.x *= wg; v.y *= wg; }
                    *(float2*)(dst + col) = v;
                }
            }
        }
    }
}

// ================= flash attention (128 q-rows, 256 threads) =================
__global__ void __launch_bounds__(256, 1) k_flash() {
    const int qt = blockIdx.x;    // 0..3
    const int h = blockIdx.y;
    const int tid = threadIdx.x;
    const int wid = tid >> 5, lane = tid & 31;
    const int g = lane >> 2, t4 = lane & 3;
    const int kvh = h >> 2;

    __shared__ __align__(16) __half Qs[128 * PADA];
    __shared__ __align__(16) __half Ks[64 * PADA];
    __shared__ __align__(16) __half Vs[64 * PADA];
    const uint32_t qU = smem_u32(Qs);
    const uint32_t kU = smem_u32(Ks);
    const uint32_t vU = smem_u32(Vs);

    for (int idx = tid; idx < 128 * 8; idx += 256) {
        int row = idx >> 3, c8 = (idx & 7) * 8;
        const float* src = g_qkv + (size_t)(qt * 128 + row) * QKVn + h * 64 + c8;
        *(uint4*)((char*)Qs + (row * PADA + c8) * 2) =
            cvt8(*(const float4*)src, *(const float4*)(src + 4));
    }
    __syncthreads();

    const int l4 = lane >> 3, lr = lane & 7;
    uint32_t qf[4][4];
    {
        int m_local = wid * 16 + (l4 & 1) * 8 + lr;
        uint32_t qAddr = qU + (uint32_t)(m_local * PADA) * 2u + (uint32_t)(l4 >> 1) * 16u;
#pragma unroll
        for (int kc = 0; kc < 4; kc++)
            ldsm_x4(qf[kc][0], qf[kc][1], qf[kc][2], qf[kc][3], qAddr + (uint32_t)kc * 32u);
    }

    uint32_t kA[4];
#pragma unroll
    for (int p = 0; p < 4; p++) {
        int n_local = p * 16 + (l4 >> 1) * 8 + lr;
        kA[p] = kU + (uint32_t)(n_local * PADA) * 2u + (uint32_t)(l4 & 1) * 16u;
    }
    uint32_t vA[4];
#pragma unroll
    for (int p = 0; p < 4; p++) {
        int k_row = (l4 & 1) * 8 + lr;
        int dh_c = p * 16 + (l4 >> 1) * 8;
        vA[p] = vU + (uint32_t)(k_row * PADA + dh_c) * 2u;
    }

    float o[8][4];
#pragma unroll
    for (int dt = 0; dt < 8; dt++)
#pragma unroll
        for (int q = 0; q < 4; q++) o[dt][q] = 0.f;
    float mrow[2] = {-3.4e38f, -3.4e38f};
    float lrow[2] = {0.f, 0.f};

    const int row0 = qt * 128 + wid * 16 + g;
    const int ktmax = 2 * qt + 1;

    for (int kt = 0; kt <= ktmax; kt++) {
        for (int idx = tid; idx < 64 * 8; idx += 256) {
            int row = idx >> 3, c8 = (idx & 7) * 8;
            const float* srck = g_qkv + (size_t)(kt * 64 + row) * QKVn + 2048 + kvh * 64 + c8;
            *(uint4*)((char*)Ks + (row * PADA + c8) * 2) =
                cvt8(*(const float4*)srck, *(const float4*)(srck + 4));
            const float* srcv = g_qkv + (size_t)(kt * 64 + row) * QKVn + 2560 + kvh * 64 + c8;
            *(uint4*)((char*)Vs + (row * PADA + c8) * 2) =
                cvt8(*(const float4*)srcv, *(const float4*)(srcv + 4));
        }
        __syncthreads();

        float s[8][4];
#pragma unroll
        for (int nt = 0; nt < 8; nt++)
#pragma unroll
            for (int q = 0; q < 4; q++) s[nt][q] = 0.f;
#pragma unroll
        for (int kc = 0; kc < 4; kc++) {
            uint32_t bf[8][2];
#pragma unroll
            for (int p = 0; p < 4; p++)
                ldsm_x4(bf[2 * p][0], bf[2 * p][1], bf[2 * p + 1][0], bf[2 * p + 1][1],
                        kA[p] + (uint32_t)kc * 32u);
#pragma unroll
            for (int nt = 0; nt < 8; nt++)
                mma_f16(s[nt], qf[kc], bf[nt]);
        }

        float alpha[2];
#pragma unroll
        for (int r = 0; r < 2; r++) {
            const int rown = row0 + r * 8;
            float mx = mrow[r];
#pragma unroll
            for (int nt = 0; nt < 8; nt++)
#pragma unroll
                for (int q = 0; q < 2; q++) {
                    int col = kt * 64 + nt * 8 + 2 * t4 + q;
                    float val = (col <= rown) ? s[nt][r * 2 + q] * 0.125f : -1e30f;
                    s[nt][r * 2 + q] = val;
                    mx = fmaxf(mx, val);
                }
            mx = fmaxf(mx, __shfl_xor_sync(0xffffffffu, mx, 1));
            mx = fmaxf(mx, __shfl_xor_sync(0xffffffffu, mx, 2));
            alpha[r] = __expf(mrow[r] - mx);
            float ls = 0.f;
#pragma unroll
            for (int nt = 0; nt < 8; nt++)
#pragma unroll
                for (int q = 0; q < 2; q++) {
                    float p = __expf(s[nt][r * 2 + q] - mx);
                    s[nt][r * 2 + q] = p;
                    ls += p;
                }
            ls += __shfl_xor_sync(0xffffffffu, ls, 1);
            ls += __shfl_xor_sync(0xffffffffu, ls, 2);
            lrow[r] = lrow[r] * alpha[r] + ls;
            mrow[r] = mx;
        }
#pragma unroll
        for (int dt = 0; dt < 8; dt++) {
            o[dt][0] *= alpha[0]; o[dt][1] *= alpha[0];
            o[dt][2] *= alpha[1]; o[dt][3] *= alpha[1];
        }

        uint32_t pf[4][4];
#pragma unroll
        for (int j = 0; j < 4; j++) {
            pf[j][0] = pack_h2(s[2 * j][0], s[2 * j][1]);
            pf[j][1] = pack_h2(s[2 * j][2], s[2 * j][3]);
            pf[j][2] = pack_h2(s[2 * j + 1][0], s[2 * j + 1][1]);
            pf[j][3] = pack_h2(s[2 * j + 1][2], s[2 * j + 1][3]);
        }
#pragma unroll
        for (int j = 0; j < 4; j++) {
            uint32_t vf[8][2];
#pragma unroll
            for (int p = 0; p < 4; p++)
                ldsm_x4_t(vf[2 * p][0], vf[2 * p][1], vf[2 * p + 1][0], vf[2 * p + 1][1],
                          vA[p] + (uint32_t)(j * 16 * PADA) * 2u);
#pragma unroll
            for (int dt = 0; dt < 8; dt++)
                mma_f16(o[dt], pf[j], vf[dt]);
        }
        __syncthreads();
    }

    float inv0 = 1.f / lrow[0];
    float inv1 = 1.f / lrow[1];
#pragma unroll
    for (int r = 0; r < 2; r++) {
        const int row = row0 + r * 8;
        float invr = r ? inv1 : inv0;
#pragma unroll
        for (int dt = 0; dt < 8; dt++) {
            int col = dt * 8 + 2 * t4;
            float* p = &g_attn[(size_t)row * Dn + h * 64 + col];
            p[0] = o[dt][r * 2 + 0] * invr;
            p[1] = o[dt][r * 2 + 1] * invr;
        }
    }
}

// ---------------- small utility kernels ----------------

__global__ void k_add_rmsnorm(const float* __restrict__ h, const float* __restrict__ r,
                              const float* __restrict__ w) {
    int t = blockIdx.x;
    if (t == 0 && threadIdx.x < En) g_cnt[threadIdx.x] = 0;
    const float* hr = h + t * Dn;
    const float* rr = r + t * Dn;
    float* resr = g_res1 + t * Dn;
    float* xr = g_x + t * Dn;

    float v[8];
    float local = 0.f;
#pragma unroll
    for (int j = 0; j < 8; j++) {
        int c = threadIdx.x + j * 256;
        float s = hr[c] + rr[c];
        v[j] = s;
        resr[c] = s;
        local += s * s;
    }
#pragma unroll
    for (int o = 16; o > 0; o >>= 1) local += __shfl_xor_sync(0xffffffffu, local, o);
    __shared__ float red[8];
    if ((threadIdx.x & 31) == 0) red[threadIdx.x >> 5] = local;
    __syncthreads();
    __shared__ float inv;
    if (threadIdx.x == 0) {
        float s = 0.f;
#pragma unroll
        for (int i = 0; i < 8; i++) s += red[i];
        inv = rsqrtf(s / (float)Dn + 1e-5f);
    }
    __syncthreads();
    float iv = inv;
#pragma unroll
    for (int j = 0; j < 8; j++) {
        int c = threadIdx.x + j * 256;
        xr[c] = v[j] * iv * w[c];
    }
}

__global__ void k_add2_rmsnorm_gate(const float* __restrict__ p0, const float* __restrict__ p1,
                                    const float* __restrict__ w, float* __restrict__ res2out,
                                    const float* __restrict__ gw) {
    int t = blockIdx.x;
    const float* a0 = p0 + t * Dn;
    const float* a1 = p1 + t * Dn;
    const float* rr = g_res1 + t * Dn;
    float* ro = res2out + t * Dn;
    float* xr = g_x2 + t * Dn;
    __shared__ float xs[Dn];
    float v[8];
    float local = 0.f;
#pragma unroll
    for (int j = 0; j < 8; j++) {
        int c = threadIdx.x + j * 256;
        float s = a0[c] + a1[c] + rr[c];
        v[j] = s;
        ro[c] = s;
        local += s * s;
    }
#pragma unroll
    for (int o = 16; o > 0; o >>= 1) local += __shfl_xor_sync(0xffffffffu, local, o);
    __shared__ float red[8];
    if ((threadIdx.x & 31) == 0) red[threadIdx.x >> 5] = local;
    __syncthreads();
    __shared__ float inv;
    if (threadIdx.x == 0) {
        float s = 0.f;
#pragma unroll
        for (int i = 0; i < 8; i++) s += red[i];
        inv = rsqrtf(s / (float)Dn + 1e-5f);
    }
    __syncthreads();
    float iv = inv;
#pragma unroll
    for (int j = 0; j < 8; j++) {
        int c = threadIdx.x + j * 256;
        float xv = v[j] * iv * w[c];
        xr[c] = xv;
        xs[c] = xv;
    }
    __syncthreads();

    const int warp = threadIdx.x >> 5, lane = threadIdx.x & 31;
    const float* wr = gw + (size_t)warp * Dn;
    float s = 0.f;
    for (int c = lane; c < Dn; c += 32) s += xs[c] * wr[c];
#pragma unroll
    for (int o = 16; o > 0; o >>= 1) s += __shfl_xor_sync(0xffffffffu, s, o);
    __shared__ float lg[En];
    if (lane == 0) lg[warp] = s;
    __syncthreads();
    if (threadIdx.x == 0) {
        int i0 = 0;
        for (int e = 1; e < En; e++) if (lg[e] > lg[i0]) i0 = e;
        int i1 = (i0 == 0) ? 1 : 0;
        for (int e = 0; e < En; e++) if (e != i0 && lg[e] > lg[i1]) i1 = e;
        float w1v = __expf(lg[i1] - lg[i0]);
        float invw = 1.f / (1.f + w1v);
        float w0 = invw, w1n = w1v * invw;
        int pp0 = atomicAdd(&g_cnt[i0], 1);
        g_tok[i0 * Tn + pp0] = t; g_wgt[i0 * Tn + pp0] = w0; g_slot[i0 * Tn + pp0] = 0;
        int pp1 = atomicAdd(&g_cnt[i1], 1);
        g_tok[i1 * Tn + pp1] = t; g_wgt[i1 * Tn + pp1] = w1n; g_slot[i1 * Tn + pp1] = 1;
    }
}

__global__ void k_rope(const float* __restrict__ cosb, const float* __restrict__ sinb) {
    int idx = blockIdx.x * 256 + threadIdx.x;
    if (idx >= Tn * 40 * 32) return;
    int d = idx & 31;
    int rest = idx >> 5;
    int hh = rest % 40;
    int t = rest / 40;
    float c = cosb[t * 32 + d];
    float s = sinb[t * 32 + d];
    float* base = g_qkv + (size_t)t * QKVn + hh * 64 + d;
    float x1 = base[0];
    float x2 = base[32];
    base[0] = x1 * c - x2 * s;
    base[32] = x2 * c + x1 * s;
}

// moe_out = sum of 4 eo slots (2 experts x 2 K-halves), float4 vectorized
__global__ void k_combine(float* __restrict__ out) {
    int i4 = blockIdx.x * 256 + threadIdx.x;      // float4 index
    if (i4 >= (Tn * Dn) / 4) return;
    int t = i4 / (Dn / 4);
    int d = i4 - t * (Dn / 4);
    const float4* base = (const float4*)(g_eo + (size_t)t * 4 * Dn) + d;
    float4 a = base[0];
    float4 b = base[Dn / 4];
    float4 c = base[2 * Dn / 4];
    float4 e = base[3 * Dn / 4];
    ((float4*)out)[i4] = make_float4(a.x + b.x + c.x + e.x, a.y + b.y + c.y + e.y,
                                     a.z + b.z + c.z + e.z, a.w + b.w + c.w + e.w);
}

// ---------------- launch ----------------
extern "C" void kernel_launch(void* const* d_in, const int* in_sizes, int n_in,
                              void* d_out, int out_size) {
    const float* hs   = (const float*)d_in[0];
    const float* resi = (const float*)d_in[1];
    const float* cosb = (const float*)d_in[2];
    const float* sinb = (const float*)d_in[3];
    const float* ln1  = (const float*)d_in[4];
    const float* ln2  = (const float*)d_in[5];
    const float* wqkv = (const float*)d_in[6];
    const float* wo   = (const float*)d_in[7];
    const float* gw   = (const float*)d_in[8];
    const float* w1   = (const float*)d_in[9];
    const float* w3   = (const float*)d_in[10];
    const float* w2   = (const float*)d_in[11];

    float* out = (float*)d_out;
    float* moe_out = out;
    float* res2 = out + Tn * Dn;

    void *px, *pqkv, *pattn, *px2, *ph1h, *peo;
    cudaGetSymbolAddress(&px, g_x);
    cudaGetSymbolAddress(&pqkv, g_qkv);
    cudaGetSymbolAddress(&pattn, g_attn);
    cudaGetSymbolAddress(&px2, g_x2);
    cudaGetSymbolAddress(&ph1h, g_h1h);
    cudaGetSymbolAddress(&peo, g_eo);

    constexpr int SMEM0 = 2 * (128 * PADH + 128 * PADH) * 2;       // 40960
    constexpr int SMEM1 = 2 * (128 * PADH + 2 * 128 * PADH) * 2;   // 61440
    constexpr int SMEM2 = 2 * (128 * PADH + 256 * PADH) * 2;       // 61440
    cudaFuncSetAttribute(k_gemm<0, 128, 1>, cudaFuncAttributeMaxDynamicSharedMemorySize, SMEM0);
    cudaFuncSetAttribute(k_gemm<0, 128, 2>, cudaFuncAttributeMaxDynamicSharedMemorySize, SMEM0);
    cudaFuncSetAttribute(k_gemm<1, 128, 1>, cudaFuncAttributeMaxDynamicSharedMemorySize, SMEM1);
    cudaFuncSetAttribute(k_gemm<2, 256, 2>, cudaFuncAttributeMaxDynamicSharedMemorySize, SMEM2);

    k_add_rmsnorm<<<Tn, 256>>>(hs, resi, ln1);

    // qkv direct: [512][3072] into g_qkv, then rope
    k_gemm<0, 128, 1><<<dim3(Tn / 128, QKVn / 128, 1), 512, SMEM0>>>(
        (const float*)px, wqkv, nullptr, (float*)pqkv, nullptr, Tn, QKVn, Dn);
    k_rope<<<(Tn * 40 * 32) / 256, 256>>>(cosb, sinb);

    // fused flash attention (scores + softmax + P@V), 128-row q tiles
    k_flash<<<dim3(Tn / 128, Hn), 256>>>();

    // attn @ wo^T partials: [2][512][2048] into g_eo; fused add + rmsnorm + gate
    k_gemm<0, 128, 2><<<dim3(Tn / 128, Dn / 128, 2), 512, SMEM0>>>(
        (const float*)pattn, wo, nullptr, (float*)peo, nullptr, Tn, Dn, Dn);
    k_add2_rmsnorm_gate<<<Tn, 256>>>((const float*)peo, (const float*)peo + Tn * Dn,
                                     ln2, res2, gw);

    // fused dual-B grouped GEMM1: h1h = fp16( silu(x@w1^T) * (x@w3^T) )
    k_gemm<1, 128, 1><<<dim3(Tn / 128, In / 128, En), 512, SMEM1>>>(
        (const float*)px2, w1, w3, (float*)ph1h, nullptr, Tn, In, Dn);
    // w2 grouped GEMM (fp16 A), split-K2, scatter into 4-slot eo
    k_gemm<2, 256, 2><<<dim3(Tn / 128, Dn / 256, En * 2), 512, SMEM2>>>(
        (const float*)ph1h, w2, nullptr, (float*)peo, nullptr, Tn, Dn, In);
    k_combine<<<(Tn * Dn / 4 + 255) / 256, 256>>>(moe_out);
}